// round 1
// baseline (speedup 1.0000x reference)
#include <cuda_runtime.h>
#include <cuda_bf16.h>
#include <math.h>

// ---------------------------------------------------------------------------
// EdgeConv restructured:
//   u = x @ theta^T            [N, 256]
//   v = x @ (phi - theta)^T    [N, 256]
//   M[s,c] = max over edges (src=s) of u[dst,c]      (CSR gather-max)
//   agg[s,c] = deg>0 ? relu(v[s,c] + M[s,c]) : 0
//   out = relu(BN(agg))
// ---------------------------------------------------------------------------

#define MAX_NODES 50000
#define MAX_EDGES 800000
#define C_IN 128
#define C_OUT 256
#define BN_EPS 1e-5f

// scratch (static device globals; no allocation allowed)
__device__ float g_u[MAX_NODES * C_OUT];
__device__ float g_v[MAX_NODES * C_OUT];
__device__ float g_wc[2 * C_OUT * C_IN];     // [512][128]: rows 0-255 theta, 256-511 phi-theta
__device__ int   g_deg[MAX_NODES];
__device__ int   g_cur[MAX_NODES];
__device__ int   g_off[MAX_NODES + 1];
__device__ int   g_dsts[MAX_EDGES];
__device__ float g_sum[C_OUT];
__device__ float g_sumsq[C_OUT];
__device__ int   g_is64;

// --------------------------- index dtype handling ---------------------------

__global__ void k_detect(const unsigned int* src_words) {
    // int64 buffer: odd 32-bit words are high halves == 0 (values in [0,50000)).
    // int32 buffer: odd words are random indices; all-zero prob ~ (1/50000)^63.
    if (threadIdx.x == 0) {
        unsigned int o = 0;
        for (int i = 1; i < 128; i += 2) o |= src_words[i];
        g_is64 = (o == 0) ? 1 : 0;
    }
}

__device__ __forceinline__ int get_idx(const void* p, int e) {
    return g_is64 ? (int)((const long long*)p)[e] : ((const int*)p)[e];
}

// --------------------------------- init ------------------------------------

__global__ void k_zero(int n) {
    int i = blockIdx.x * blockDim.x + threadIdx.x;
    if (i < n) { g_deg[i] = 0; g_cur[i] = 0; }
    if (i < C_OUT) { g_sum[i] = 0.0f; g_sumsq[i] = 0.0f; }
}

__global__ void k_wcomb(const float* __restrict__ theta, const float* __restrict__ phi) {
    int j = blockIdx.x;      // 0..511
    int t = threadIdx.x;     // 0..127
    float w;
    if (j < C_OUT) w = theta[j * C_IN + t];
    else           w = phi[(j - C_OUT) * C_IN + t] - theta[(j - C_OUT) * C_IN + t];
    g_wc[j * C_IN + t] = w;
}

// ------------------------------ CSR build ----------------------------------

__global__ void k_degree(const void* src, int E) {
    int e = blockIdx.x * blockDim.x + threadIdx.x;
    if (e < E) atomicAdd(&g_deg[get_idx(src, e)], 1);
}

// single-CTA exclusive scan over g_deg[0..n) -> g_off, g_off[n] = E
__global__ void k_scan(int n) {
    __shared__ int wsum[32];
    int t = threadIdx.x, lane = t & 31, wid = t >> 5;
    int carry = 0;
    for (int base = 0; base < n; base += 1024) {
        int i = base + t;
        int v = (i < n) ? g_deg[i] : 0;
        int x = v;
        #pragma unroll
        for (int o = 1; o < 32; o <<= 1) {
            int nb = __shfl_up_sync(0xffffffffu, x, o);
            if (lane >= o) x += nb;
        }
        if (lane == 31) wsum[wid] = x;
        __syncthreads();
        if (wid == 0) {
            int s = wsum[lane];
            #pragma unroll
            for (int o = 1; o < 32; o <<= 1) {
                int nb = __shfl_up_sync(0xffffffffu, s, o);
                if (lane >= o) s += nb;
            }
            wsum[lane] = s;
        }
        __syncthreads();
        int warpoff = (wid == 0) ? 0 : wsum[wid - 1];
        int incl = warpoff + x;
        if (i < n) g_off[i] = carry + incl - v;
        int total = wsum[31];
        __syncthreads();
        carry += total;
    }
    if (t == 0) g_off[n] = carry;
}

__global__ void k_scatter(const void* src, const void* dst, int E) {
    int e = blockIdx.x * blockDim.x + threadIdx.x;
    if (e < E) {
        int s = get_idx(src, e);
        int d = get_idx(dst, e);
        int p = atomicAdd(&g_cur[s], 1);
        g_dsts[g_off[s] + p] = d;
    }
}

// --------------------------------- GEMM ------------------------------------
// C[n, 512] = x[n,128] @ g_wc[512,128]^T, split into g_u (cols 0-255) and
// g_v (cols 256-511). BM=128, BN=64, BK=32, 256 threads, 8x4 per thread.

#define BM 128
#define BN 64
#define BK 32

__global__ __launch_bounds__(256) void k_gemm(const float* __restrict__ x, int n) {
    __shared__ float sx[BK][BM + 4];
    __shared__ float sw[BK][BN + 4];
    int m0 = blockIdx.x * BM;
    int n0 = blockIdx.y * BN;
    int tid = threadIdx.x;
    int tx = tid & 15;   // col group: 4 cols each
    int ty = tid >> 4;   // row group: 8 rows each

    float acc[8][4];
    #pragma unroll
    for (int a = 0; a < 8; a++)
        #pragma unroll
        for (int b = 0; b < 4; b++) acc[a][b] = 0.0f;

    int xr  = tid >> 1;          // 0..127 (x row within tile)
    int xj0 = (tid & 1) * 16;    // k-subrange start for x loads
    int wr  = tid >> 2;          // 0..63  (w row within tile)
    int wj0 = (tid & 3) * 8;     // k-subrange start for w loads

    for (int kc = 0; kc < C_IN; kc += BK) {
        int gm = m0 + xr;
        if (gm < n) {
            const float4* xp = (const float4*)(x + (size_t)gm * C_IN + kc + xj0);
            #pragma unroll
            for (int q = 0; q < 4; q++) {
                float4 vv = xp[q];
                int jj = xj0 + q * 4;
                sx[jj + 0][xr] = vv.x; sx[jj + 1][xr] = vv.y;
                sx[jj + 2][xr] = vv.z; sx[jj + 3][xr] = vv.w;
            }
        } else {
            #pragma unroll
            for (int q = 0; q < 4; q++) {
                int jj = xj0 + q * 4;
                sx[jj][xr] = 0.0f; sx[jj + 1][xr] = 0.0f;
                sx[jj + 2][xr] = 0.0f; sx[jj + 3][xr] = 0.0f;
            }
        }
        const float4* wp = (const float4*)(g_wc + (size_t)(n0 + wr) * C_IN + kc + wj0);
        #pragma unroll
        for (int q = 0; q < 2; q++) {
            float4 vv = wp[q];
            int jj = wj0 + q * 4;
            sw[jj + 0][wr] = vv.x; sw[jj + 1][wr] = vv.y;
            sw[jj + 2][wr] = vv.z; sw[jj + 3][wr] = vv.w;
        }
        __syncthreads();

        #pragma unroll
        for (int j = 0; j < BK; j++) {
            float4 xa = *(const float4*)&sx[j][ty * 8];
            float4 xb = *(const float4*)&sx[j][ty * 8 + 4];
            float4 wv = *(const float4*)&sw[j][tx * 4];
            float xs_[8] = {xa.x, xa.y, xa.z, xa.w, xb.x, xb.y, xb.z, xb.w};
            float ws_[4] = {wv.x, wv.y, wv.z, wv.w};
            #pragma unroll
            for (int a = 0; a < 8; a++)
                #pragma unroll
                for (int b = 0; b < 4; b++)
                    acc[a][b] += xs_[a] * ws_[b];
        }
        __syncthreads();
    }

    // store (whole BN tile lies entirely in u or entirely in v)
    float* basep = (blockIdx.y < 4) ? g_u : g_v;
    int nloc = ((blockIdx.y < 4) ? n0 : (n0 - C_OUT)) + tx * 4;
    #pragma unroll
    for (int a = 0; a < 8; a++) {
        int m = m0 + ty * 8 + a;
        if (m < n) {
            float4 o = make_float4(acc[a][0], acc[a][1], acc[a][2], acc[a][3]);
            *(float4*)&basep[(size_t)m * C_OUT + nloc] = o;
        }
    }
}

// ----------------------------- edge gather-max ------------------------------
// one CTA per node, 256 threads = 256 channels; agg written to d_out

__global__ __launch_bounds__(256) void k_edge(float* __restrict__ out) {
    int s = blockIdx.x;
    int t = threadIdx.x;
    int start = g_off[s], end = g_off[s + 1];
    float m = -INFINITY;
    int i = start;
    for (; i + 4 <= end; i += 4) {
        int d0 = g_dsts[i], d1 = g_dsts[i + 1], d2 = g_dsts[i + 2], d3 = g_dsts[i + 3];
        float a = g_u[(size_t)d0 * C_OUT + t];
        float b = g_u[(size_t)d1 * C_OUT + t];
        float c = g_u[(size_t)d2 * C_OUT + t];
        float d = g_u[(size_t)d3 * C_OUT + t];
        m = fmaxf(m, fmaxf(fmaxf(a, b), fmaxf(c, d)));
    }
    for (; i < end; i++) m = fmaxf(m, g_u[(size_t)g_dsts[i] * C_OUT + t]);
    float r = (end > start) ? fmaxf(g_v[(size_t)s * C_OUT + t] + m, 0.0f) : 0.0f;
    out[(size_t)s * C_OUT + t] = r;
}

// --------------------------------- BN ---------------------------------------

__global__ void k_bnstat(const float* __restrict__ agg, int n) {
    int t = threadIdx.x;                 // channel
    int r0 = blockIdx.x * 256;
    int r1 = min(r0 + 256, n);
    float s = 0.0f, s2 = 0.0f;
    for (int r = r0; r < r1; r++) {
        float v = agg[(size_t)r * C_OUT + t];
        s += v; s2 += v * v;
    }
    atomicAdd(&g_sum[t], s);
    atomicAdd(&g_sumsq[t], s2);
}

__global__ void k_bnapply(float* __restrict__ out,
                          const float* __restrict__ gamma,
                          const float* __restrict__ beta, int n) {
    int t = threadIdx.x;
    int s = blockIdx.x;
    float inv_n = 1.0f / (float)n;
    float mean = g_sum[t] * inv_n;
    float var  = g_sumsq[t] * inv_n - mean * mean;
    float rs = rsqrtf(var + BN_EPS);
    float v = out[(size_t)s * C_OUT + t];
    float y = (v - mean) * rs * gamma[t] + beta[t];
    out[(size_t)s * C_OUT + t] = fmaxf(y, 0.0f);
}

// -------------------------------- launcher ----------------------------------

extern "C" void kernel_launch(void* const* d_in, const int* in_sizes, int n_in,
                              void* d_out, int out_size) {
    const float* x     = (const float*)d_in[0];
    const void*  src   = d_in[1];
    const void*  dst   = d_in[2];
    const float* theta = (const float*)d_in[3];
    const float* phi   = (const float*)d_in[4];
    const float* gamma = (const float*)d_in[5];
    const float* beta  = (const float*)d_in[6];
    float* out = (float*)d_out;

    int n = in_sizes[0] / C_IN;     // 50000
    int E = in_sizes[1];            // 800000 (element count, dtype-agnostic)

    k_detect<<<1, 32>>>((const unsigned int*)src);
    k_zero<<<(n + 255) / 256, 256>>>(n);
    k_wcomb<<<2 * C_OUT, C_IN>>>(theta, phi);
    k_degree<<<(E + 255) / 256, 256>>>(src, E);
    k_scan<<<1, 1024>>>(n);
    k_scatter<<<(E + 255) / 256, 256>>>(src, dst, E);
    dim3 ggrid((n + BM - 1) / BM, (2 * C_OUT) / BN);
    k_gemm<<<ggrid, 256>>>(x, n);
    k_edge<<<n, 256>>>(out);
    k_bnstat<<<(n + 255) / 256, 256>>>(out, n);
    k_bnapply<<<n, 256>>>(out, gamma, beta, n);
}

// round 2
// speedup vs baseline: 1.1449x; 1.1449x over previous
#include <cuda_runtime.h>
#include <cuda_bf16.h>
#include <math.h>

// ---------------------------------------------------------------------------
// EdgeConv restructured:
//   u = x @ theta^T            [N, 256]
//   v = x @ (phi - theta)^T    [N, 256]
//   M[s,c] = max over edges (src=s) of u[dst,c]      (CSR gather-max)
//   agg[s,c] = deg>0 ? relu(v[s,c] + M[s,c]) : 0
//   out = relu(BN(agg))
// GEMM uses packed fma.rn.f32x2 (sm_103a): 2x fp32 FMA per issue slot.
// ---------------------------------------------------------------------------

#define MAX_NODES 50000
#define MAX_EDGES 800000
#define C_IN 128
#define C_OUT 256
#define BN_EPS 1e-5f

__device__ float g_u[MAX_NODES * C_OUT];
__device__ float g_v[MAX_NODES * C_OUT];
__device__ float g_wc[2 * C_OUT * C_IN];     // [512][128]: rows 0-255 theta, 256-511 phi-theta
__device__ int   g_deg[MAX_NODES];
__device__ int   g_cur[MAX_NODES];
__device__ int   g_off[MAX_NODES + 1];
__device__ int   g_dsts[MAX_EDGES];
__device__ float g_sum[C_OUT];
__device__ float g_sumsq[C_OUT];
__device__ float g_scale[C_OUT];
__device__ float g_bias[C_OUT];
__device__ int   g_is64;

// --------------------------- index dtype handling ---------------------------

__global__ void k_detect(const unsigned int* src_words) {
    if (threadIdx.x == 0) {
        unsigned int o = 0;
        for (int i = 1; i < 128; i += 2) o |= src_words[i];
        g_is64 = (o == 0) ? 1 : 0;
    }
}

__device__ __forceinline__ int get_idx(const void* p, int e) {
    return g_is64 ? (int)((const long long*)p)[e] : ((const int*)p)[e];
}

// --------------------------------- init ------------------------------------

__global__ void k_zero(int n) {
    int i = blockIdx.x * blockDim.x + threadIdx.x;
    if (i < n) { g_deg[i] = 0; g_cur[i] = 0; }
    if (i < C_OUT) { g_sum[i] = 0.0f; g_sumsq[i] = 0.0f; }
}

__global__ void k_wcomb(const float* __restrict__ theta, const float* __restrict__ phi) {
    int j = blockIdx.x;      // 0..511
    int t = threadIdx.x;     // 0..127
    float w;
    if (j < C_OUT) w = theta[j * C_IN + t];
    else           w = phi[(j - C_OUT) * C_IN + t] - theta[(j - C_OUT) * C_IN + t];
    g_wc[j * C_IN + t] = w;
}

// ------------------------------ CSR build ----------------------------------

__global__ void k_degree(const void* src, int E) {
    int e = blockIdx.x * blockDim.x + threadIdx.x;
    if (e < E) atomicAdd(&g_deg[get_idx(src, e)], 1);
}

__global__ void k_scan(int n) {
    __shared__ int wsum[32];
    int t = threadIdx.x, lane = t & 31, wid = t >> 5;
    int carry = 0;
    for (int base = 0; base < n; base += 1024) {
        int i = base + t;
        int v = (i < n) ? g_deg[i] : 0;
        int x = v;
        #pragma unroll
        for (int o = 1; o < 32; o <<= 1) {
            int nb = __shfl_up_sync(0xffffffffu, x, o);
            if (lane >= o) x += nb;
        }
        if (lane == 31) wsum[wid] = x;
        __syncthreads();
        if (wid == 0) {
            int s = wsum[lane];
            #pragma unroll
            for (int o = 1; o < 32; o <<= 1) {
                int nb = __shfl_up_sync(0xffffffffu, s, o);
                if (lane >= o) s += nb;
            }
            wsum[lane] = s;
        }
        __syncthreads();
        int warpoff = (wid == 0) ? 0 : wsum[wid - 1];
        int incl = warpoff + x;
        if (i < n) g_off[i] = carry + incl - v;
        int total = wsum[31];
        __syncthreads();
        carry += total;
    }
    if (t == 0) g_off[n] = carry;
}

__global__ void k_scatter(const void* src, const void* dst, int E) {
    int e = blockIdx.x * blockDim.x + threadIdx.x;
    if (e < E) {
        int s = get_idx(src, e);
        int d = get_idx(dst, e);
        int p = atomicAdd(&g_cur[s], 1);
        g_dsts[g_off[s] + p] = d;
    }
}

// --------------------------------- GEMM ------------------------------------
// C[n, 512] = x[n,128] @ g_wc[512,128]^T  -> g_u (cols 0-255) / g_v (256-511).
// BM=128, BN=64, BK=32, 256 threads; per-thread 8 rows x 4 cols as
// 4 row-pairs x 4 cols accumulated with fma.rn.f32x2.
// x tile transposed [k][m] -> row-pairs are contiguous 64-bit shared loads.
// w tile stored pair-DUPLICATED in two 64-float planes for conflict-light loads.

#define BM 128
#define BN 64
#define BK 32

typedef unsigned long long ull;

__device__ __forceinline__ void fma2(ull& d, ull a, ull b) {
    asm("fma.rn.f32x2 %0, %1, %2, %0;" : "+l"(d) : "l"(a), "l"(b));
}
__device__ __forceinline__ float f2lo(ull v) { return __uint_as_float((unsigned)v); }
__device__ __forceinline__ float f2hi(ull v) { return __uint_as_float((unsigned)(v >> 32)); }

__global__ __launch_bounds__(256) void k_gemm(const float* __restrict__ x, int n) {
    __shared__ __align__(16) float sx[BK][BM + 4];
    __shared__ __align__(16) float swd[BK][132];   // [0..63]=plane0 (b0,b1 dup), [64..127]=plane1 (b2,b3 dup)
    int m0 = blockIdx.x * BM;
    int n0 = blockIdx.y * BN;
    int tid = threadIdx.x;
    int tx = tid & 15;   // col group: 4 cols each
    int ty = tid >> 4;   // row group: 8 rows each

    ull acc2[4][4];
    #pragma unroll
    for (int a = 0; a < 4; a++)
        #pragma unroll
        for (int b = 0; b < 4; b++) acc2[a][b] = 0ULL;

    int xr  = tid >> 1;          // 0..127 x row within tile
    int xj0 = (tid & 1) * 16;    // k-subrange for x loads
    int wr  = tid >> 2;          // 0..63  w row (col of output) within tile
    int wj0 = (tid & 3) * 8;     // k-subrange for w loads
    // duplicated store position for w value (col pi=wr):
    int wtxg = wr >> 2, wb = wr & 3;
    int wpos = (wb >> 1) * 64 + wtxg * 4 + (wb & 1) * 2;

    for (int kc = 0; kc < C_IN; kc += BK) {
        int gm = m0 + xr;
        if (gm < n) {
            const float4* xp = (const float4*)(x + (size_t)gm * C_IN + kc + xj0);
            #pragma unroll
            for (int q = 0; q < 4; q++) {
                float4 vv = xp[q];
                int jj = xj0 + q * 4;
                sx[jj + 0][xr] = vv.x; sx[jj + 1][xr] = vv.y;
                sx[jj + 2][xr] = vv.z; sx[jj + 3][xr] = vv.w;
            }
        } else {
            #pragma unroll
            for (int q = 0; q < 4; q++) {
                int jj = xj0 + q * 4;
                sx[jj][xr] = 0.0f; sx[jj + 1][xr] = 0.0f;
                sx[jj + 2][xr] = 0.0f; sx[jj + 3][xr] = 0.0f;
            }
        }
        const float4* wp = (const float4*)(g_wc + (size_t)(n0 + wr) * C_IN + kc + wj0);
        #pragma unroll
        for (int q = 0; q < 2; q++) {
            float4 vv = wp[q];
            int jj = wj0 + q * 4;
            swd[jj + 0][wpos] = vv.x; swd[jj + 0][wpos + 1] = vv.x;
            swd[jj + 1][wpos] = vv.y; swd[jj + 1][wpos + 1] = vv.y;
            swd[jj + 2][wpos] = vv.z; swd[jj + 2][wpos + 1] = vv.z;
            swd[jj + 3][wpos] = vv.w; swd[jj + 3][wpos + 1] = vv.w;
        }
        __syncthreads();

        #pragma unroll
        for (int j = 0; j < BK; j++) {
            ulonglong2 x01 = *(const ulonglong2*)&sx[j][ty * 8];
            ulonglong2 x23 = *(const ulonglong2*)&sx[j][ty * 8 + 4];
            ulonglong2 w01 = *(const ulonglong2*)&swd[j][tx * 4];
            ulonglong2 w23 = *(const ulonglong2*)&swd[j][64 + tx * 4];
            ull xq0 = x01.x, xq1 = x01.y, xq2 = x23.x, xq3 = x23.y;
            ull wq0 = w01.x, wq1 = w01.y, wq2 = w23.x, wq3 = w23.y;
            fma2(acc2[0][0], xq0, wq0); fma2(acc2[0][1], xq0, wq1);
            fma2(acc2[0][2], xq0, wq2); fma2(acc2[0][3], xq0, wq3);
            fma2(acc2[1][0], xq1, wq0); fma2(acc2[1][1], xq1, wq1);
            fma2(acc2[1][2], xq1, wq2); fma2(acc2[1][3], xq1, wq3);
            fma2(acc2[2][0], xq2, wq0); fma2(acc2[2][1], xq2, wq1);
            fma2(acc2[2][2], xq2, wq2); fma2(acc2[2][3], xq2, wq3);
            fma2(acc2[3][0], xq3, wq0); fma2(acc2[3][1], xq3, wq1);
            fma2(acc2[3][2], xq3, wq2); fma2(acc2[3][3], xq3, wq3);
        }
        __syncthreads();
    }

    float* basep = (blockIdx.y < 4) ? g_u : g_v;
    int nloc = ((blockIdx.y < 4) ? n0 : (n0 - C_OUT)) + tx * 4;
    #pragma unroll
    for (int a = 0; a < 4; a++) {
        int r0 = m0 + ty * 8 + 2 * a;
        if (r0 < n) {
            float4 lo = make_float4(f2lo(acc2[a][0]), f2lo(acc2[a][1]),
                                    f2lo(acc2[a][2]), f2lo(acc2[a][3]));
            *(float4*)&basep[(size_t)r0 * C_OUT + nloc] = lo;
        }
        if (r0 + 1 < n) {
            float4 hi = make_float4(f2hi(acc2[a][0]), f2hi(acc2[a][1]),
                                    f2hi(acc2[a][2]), f2hi(acc2[a][3]));
            *(float4*)&basep[(size_t)(r0 + 1) * C_OUT + nloc] = hi;
        }
    }
}

// ----------------------------- edge gather-max ------------------------------
// one CTA (64 threads) per node; thread t owns channels 4t..4t+3 (float4).
// unroll-8 keeps 8 independent 16B row loads in flight.

__device__ __forceinline__ void max4(float4& m, float4 r) {
    m.x = fmaxf(m.x, r.x); m.y = fmaxf(m.y, r.y);
    m.z = fmaxf(m.z, r.z); m.w = fmaxf(m.w, r.w);
}

__global__ __launch_bounds__(64) void k_edge(float* __restrict__ out) {
    int s = blockIdx.x;
    int t = threadIdx.x;
    int start = g_off[s], end = g_off[s + 1];
    float4 m = make_float4(-INFINITY, -INFINITY, -INFINITY, -INFINITY);
    int i = start;
    for (; i + 8 <= end; i += 8) {
        int d[8];
        #pragma unroll
        for (int q = 0; q < 8; q++) d[q] = g_dsts[i + q];
        float4 r[8];
        #pragma unroll
        for (int q = 0; q < 8; q++)
            r[q] = ((const float4*)&g_u[(size_t)d[q] * C_OUT])[t];
        #pragma unroll
        for (int q = 0; q < 8; q++) max4(m, r[q]);
    }
    for (; i < end; i++) {
        float4 r = ((const float4*)&g_u[(size_t)g_dsts[i] * C_OUT])[t];
        max4(m, r);
    }
    float4 res;
    if (end > start) {
        float4 v = ((const float4*)&g_v[(size_t)s * C_OUT])[t];
        res.x = fmaxf(v.x + m.x, 0.0f);
        res.y = fmaxf(v.y + m.y, 0.0f);
        res.z = fmaxf(v.z + m.z, 0.0f);
        res.w = fmaxf(v.w + m.w, 0.0f);
    } else {
        res = make_float4(0.0f, 0.0f, 0.0f, 0.0f);
    }
    ((float4*)out)[(size_t)s * 64 + t] = res;
}

// --------------------------------- BN ---------------------------------------

__global__ void k_bnstat(const float* __restrict__ agg, int n) {
    int t = threadIdx.x;                 // channel
    int r0 = blockIdx.x * 256;
    int r1 = min(r0 + 256, n);
    float s = 0.0f, s2 = 0.0f;
    for (int r = r0; r < r1; r++) {
        float v = agg[(size_t)r * C_OUT + t];
        s += v; s2 += v * v;
    }
    atomicAdd(&g_sum[t], s);
    atomicAdd(&g_sumsq[t], s2);
}

__global__ void k_bnfin(const float* __restrict__ gamma,
                        const float* __restrict__ beta, int n) {
    int t = threadIdx.x;
    float inv_n = 1.0f / (float)n;
    float mean = g_sum[t] * inv_n;
    float var  = g_sumsq[t] * inv_n - mean * mean;
    float rs = rsqrtf(var + BN_EPS);
    float sc = rs * gamma[t];
    g_scale[t] = sc;
    g_bias[t]  = beta[t] - mean * sc;
}

__global__ void k_bnapply(float4* __restrict__ out, int total4) {
    int i = blockIdx.x * blockDim.x + threadIdx.x;
    if (i < total4) {
        int c = i & 63;
        float4 v  = out[i];
        float4 sc = ((const float4*)g_scale)[c];
        float4 bi = ((const float4*)g_bias)[c];
        v.x = fmaxf(fmaf(v.x, sc.x, bi.x), 0.0f);
        v.y = fmaxf(fmaf(v.y, sc.y, bi.y), 0.0f);
        v.z = fmaxf(fmaf(v.z, sc.z, bi.z), 0.0f);
        v.w = fmaxf(fmaf(v.w, sc.w, bi.w), 0.0f);
        out[i] = v;
    }
}

// -------------------------------- launcher ----------------------------------

extern "C" void kernel_launch(void* const* d_in, const int* in_sizes, int n_in,
                              void* d_out, int out_size) {
    const float* x     = (const float*)d_in[0];
    const void*  src   = d_in[1];
    const void*  dst   = d_in[2];
    const float* theta = (const float*)d_in[3];
    const float* phi   = (const float*)d_in[4];
    const float* gamma = (const float*)d_in[5];
    const float* beta  = (const float*)d_in[6];
    float* out = (float*)d_out;

    int n = in_sizes[0] / C_IN;     // 50000
    int E = in_sizes[1];            // 800000

    k_detect<<<1, 32>>>((const unsigned int*)src);
    k_zero<<<(n + 255) / 256, 256>>>(n);
    k_wcomb<<<2 * C_OUT, C_IN>>>(theta, phi);
    dim3 ggrid((n + BM - 1) / BM, (2 * C_OUT) / BN);
    k_gemm<<<ggrid, 256>>>(x, n);                    // at captured launch index
    k_degree<<<(E + 255) / 256, 256>>>(src, E);
    k_scan<<<1, 1024>>>(n);
    k_scatter<<<(E + 255) / 256, 256>>>(src, dst, E);
    k_edge<<<n, 64>>>(out);
    k_bnstat<<<(n + 255) / 256, 256>>>(out, n);
    k_bnfin<<<1, C_OUT>>>(gamma, beta, n);
    int total4 = n * 64;
    k_bnapply<<<(total4 + 255) / 256, 256>>>((float4*)out, total4);
}

// round 4
// speedup vs baseline: 1.8079x; 1.5791x over previous
#include <cuda_runtime.h>
#include <cuda_bf16.h>
#include <math.h>
#include <stdint.h>

// ---------------------------------------------------------------------------
// EdgeConv restructured:
//   u = x @ theta^T            [N, 256]
//   v = x @ (phi - theta)^T    [N, 256]
//   M[s,c] = max over edges (src=s) of u[dst,c]      (CSR gather-max)
//   agg[s,c] = deg>0 ? relu(v[s,c] + M[s,c]) : 0
//   out = relu(BN(agg))
// GEMM: mma.sync bf16 (HMMA), split precision via K-concat:
//   [n,512] = [xh,xh,xl]([n,384]) @ [wh,wl,wh]^T([512,384]), fp32 accum.
// ---------------------------------------------------------------------------

#define MAX_NODES 50000
#define MAX_EDGES 800000
#define C_IN 128
#define C_OUT 256
#define BN_EPS 1e-5f

__device__ float    g_u[MAX_NODES * C_OUT];
__device__ float    g_v[MAX_NODES * C_OUT];
__device__ uint32_t g_wc[512 * 192];   // bf16 pairs: [512 rows][384 cols] = [wh | wl | wh]
__device__ int      g_deg[MAX_NODES];
__device__ int      g_cur[MAX_NODES];
__device__ int      g_off[MAX_NODES + 1];
__device__ int      g_dsts[MAX_EDGES];
__device__ float    g_sum[C_OUT];
__device__ float    g_sumsq[C_OUT];
__device__ float    g_scale[C_OUT];
__device__ float    g_bias[C_OUT];
__device__ int      g_is64;

// --------------------------- index dtype handling ---------------------------

__global__ void k_detect(const unsigned int* src_words) {
    if (threadIdx.x == 0) {
        unsigned int o = 0;
        for (int i = 1; i < 128; i += 2) o |= src_words[i];
        g_is64 = (o == 0) ? 1 : 0;
    }
}
__device__ __forceinline__ int get_idx(const void* p, int e) {
    return g_is64 ? (int)((const long long*)p)[e] : ((const int*)p)[e];
}

// --------------------------------- init ------------------------------------

__global__ void k_zero(int n) {
    int i = blockIdx.x * blockDim.x + threadIdx.x;
    if (i < n) { g_deg[i] = 0; g_cur[i] = 0; }
    if (i < C_OUT) { g_sum[i] = 0.0f; g_sumsq[i] = 0.0f; }
}

// build concat weight table: row j (0-255: theta, 256-511: phi-theta),
// col segments [0:128)=hi, [128:256)=lo, [256:384)=hi
__global__ void k_wsplit(const float* __restrict__ theta, const float* __restrict__ phi) {
    int j = blockIdx.x;      // 0..511
    int p = threadIdx.x;     // 0..191 (bf16 pair index)
    int seg = p >> 6;        // 0,1,2
    int kk = (p & 63) * 2;
    float w0, w1;
    if (j < C_OUT) {
        w0 = theta[j * C_IN + kk];
        w1 = theta[j * C_IN + kk + 1];
    } else {
        int jj = j - C_OUT;
        w0 = phi[jj * C_IN + kk]     - theta[jj * C_IN + kk];
        w1 = phi[jj * C_IN + kk + 1] - theta[jj * C_IN + kk + 1];
    }
    __nv_bfloat16 h0 = __float2bfloat16(w0), h1 = __float2bfloat16(w1);
    uint32_t out;
    if (seg == 1) {
        __nv_bfloat16 l0 = __float2bfloat16(w0 - __bfloat162float(h0));
        __nv_bfloat16 l1 = __float2bfloat16(w1 - __bfloat162float(h1));
        out = (uint32_t)__bfloat16_as_ushort(l0) | ((uint32_t)__bfloat16_as_ushort(l1) << 16);
    } else {
        out = (uint32_t)__bfloat16_as_ushort(h0) | ((uint32_t)__bfloat16_as_ushort(h1) << 16);
    }
    g_wc[j * 192 + p] = out;
}

// ------------------------------ HMMA GEMM -----------------------------------
// CTA 128x128, K'=384 in 6 chunks of 64. smem rows padded to 72 bf16 (144 B)
// so ldmatrix row addresses are bank-conflict-free.

#define SROW 72

__device__ __forceinline__ uint32_t smem_u32(const void* p) {
    uint32_t a;
    asm("{ .reg .u64 t; cvta.to.shared.u64 t, %1; cvt.u32.u64 %0, t; }" : "=r"(a) : "l"(p));
    return a;
}

__device__ __forceinline__ void ldsm4(uint32_t& r0, uint32_t& r1, uint32_t& r2, uint32_t& r3,
                                      uint32_t addr) {
    asm volatile("ldmatrix.sync.aligned.m8n8.x4.shared.b16 {%0,%1,%2,%3}, [%4];"
                 : "=r"(r0), "=r"(r1), "=r"(r2), "=r"(r3) : "r"(addr));
}

__device__ __forceinline__ void mma16816(float* c, uint32_t a0, uint32_t a1, uint32_t a2,
                                         uint32_t a3, uint32_t b0, uint32_t b1) {
    asm volatile(
        "mma.sync.aligned.m16n8k16.row.col.f32.bf16.bf16.f32 "
        "{%0,%1,%2,%3}, {%4,%5,%6,%7}, {%8,%9}, {%0,%1,%2,%3};"
        : "+f"(c[0]), "+f"(c[1]), "+f"(c[2]), "+f"(c[3])
        : "r"(a0), "r"(a1), "r"(a2), "r"(a3), "r"(b0), "r"(b1));
}

__global__ __launch_bounds__(256) void k_gemm_mma(const float* __restrict__ x, int n) {
    __shared__ __align__(16) __nv_bfloat16 sA[128][SROW];
    __shared__ __align__(16) __nv_bfloat16 sB[128][SROW];

    int tid = threadIdx.x;
    int wid = tid >> 5, lane = tid & 31;
    int m0 = blockIdx.x * 128;
    int n0 = blockIdx.y * 128;        // within [0, 512)
    int wm = wid & 3, wn = wid >> 2;  // warp 32 rows x 64 cols

    float acc[2][8][4];
    #pragma unroll
    for (int a = 0; a < 2; a++)
        #pragma unroll
        for (int b = 0; b < 8; b++)
            #pragma unroll
            for (int q = 0; q < 4; q++) acc[a][b][q] = 0.0f;

    uint32_t sAb = smem_u32(&sA[0][0]);
    uint32_t sBb = smem_u32(&sB[0][0]);

    // precompute ldmatrix lane addresses
    // A: tile at (warp row base + mt*16, kk*16):
    uint32_t a_lane_row = (uint32_t)(wm * 32 + (lane & 15));
    uint32_t a_lane_kh  = (uint32_t)((lane >> 4) * 8);
    // B: lanes: n-row = wn*64 + np*16 + (l>>4)*8 + (l&7); khalf = ((l>>3)&1)*8
    uint32_t b_lane_row = (uint32_t)(wn * 64 + ((lane >> 4) * 8) + (lane & 7));
    uint32_t b_lane_kh  = (uint32_t)(((lane >> 3) & 1) * 8);

    for (int c = 0; c < 6; c++) {
        int term = c >> 1;                 // 0,1: xh ; 2: xl
        int xcol0 = (c & 1) * 64;
        // ---- fill A: 128 rows x 16 float4 (64 floats) ----
        #pragma unroll
        for (int it = 0; it < 8; it++) {
            int i = it * 256 + tid;        // 0..2047
            int row = i >> 4, q = i & 15;
            float4 xv;
            if (m0 + row < n)
                xv = *(const float4*)&x[(size_t)(m0 + row) * C_IN + xcol0 + q * 4];
            else
                xv = make_float4(0.f, 0.f, 0.f, 0.f);
            __nv_bfloat16 h0 = __float2bfloat16(xv.x), h1 = __float2bfloat16(xv.y);
            __nv_bfloat16 h2 = __float2bfloat16(xv.z), h3 = __float2bfloat16(xv.w);
            uint32_t p0, p1;
            if (term < 2) {
                p0 = (uint32_t)__bfloat16_as_ushort(h0) | ((uint32_t)__bfloat16_as_ushort(h1) << 16);
                p1 = (uint32_t)__bfloat16_as_ushort(h2) | ((uint32_t)__bfloat16_as_ushort(h3) << 16);
            } else {
                __nv_bfloat16 l0 = __float2bfloat16(xv.x - __bfloat162float(h0));
                __nv_bfloat16 l1 = __float2bfloat16(xv.y - __bfloat162float(h1));
                __nv_bfloat16 l2 = __float2bfloat16(xv.z - __bfloat162float(h2));
                __nv_bfloat16 l3 = __float2bfloat16(xv.w - __bfloat162float(h3));
                p0 = (uint32_t)__bfloat16_as_ushort(l0) | ((uint32_t)__bfloat16_as_ushort(l1) << 16);
                p1 = (uint32_t)__bfloat16_as_ushort(l2) | ((uint32_t)__bfloat16_as_ushort(l3) << 16);
            }
            uint2 st = make_uint2(p0, p1);
            *(uint2*)((char*)&sA[0][0] + row * (SROW * 2) + q * 8) = st;
        }
        // ---- fill B: rows n0..n0+127, pairs c*32 .. +31 (uint4 = 4 pairs) ----
        #pragma unroll
        for (int it = 0; it < 4; it++) {
            int i = it * 256 + tid;        // 0..1023
            int row = i >> 3, q = i & 7;   // 8 uint4 per row
            uint4 wv = *(const uint4*)&g_wc[(size_t)(n0 + row) * 192 + c * 32 + q * 4];
            *(uint4*)((char*)&sB[0][0] + row * (SROW * 2) + q * 16) = wv;
        }
        __syncthreads();

        #pragma unroll
        for (int kk = 0; kk < 4; kk++) {
            uint32_t af[2][4];
            #pragma unroll
            for (int mt = 0; mt < 2; mt++) {
                uint32_t addr = sAb + (a_lane_row + mt * 16) * (SROW * 2)
                              + (kk * 16 + a_lane_kh) * 2;
                ldsm4(af[mt][0], af[mt][1], af[mt][2], af[mt][3], addr);
            }
            uint32_t bf[8][2];
            #pragma unroll
            for (int np = 0; np < 4; np++) {
                uint32_t addr = sBb + (b_lane_row + np * 16) * (SROW * 2)
                              + (kk * 16 + b_lane_kh) * 2;
                uint32_t r0, r1, r2, r3;
                ldsm4(r0, r1, r2, r3, addr);
                bf[np * 2][0] = r0; bf[np * 2][1] = r1;
                bf[np * 2 + 1][0] = r2; bf[np * 2 + 1][1] = r3;
            }
            #pragma unroll
            for (int mt = 0; mt < 2; mt++)
                #pragma unroll
                for (int nt = 0; nt < 8; nt++)
                    mma16816(acc[mt][nt], af[mt][0], af[mt][1], af[mt][2], af[mt][3],
                             bf[nt][0], bf[nt][1]);
        }
        __syncthreads();
    }

    // ---- epilogue ----
    int g = lane >> 2, tig = lane & 3;
    float* outp = (blockIdx.y < 2) ? g_u : g_v;
    int colbase = (int)(blockIdx.y & 1) * 128 + wn * 64 + tig * 2;
    #pragma unroll
    for (int mt = 0; mt < 2; mt++) {
        int r0 = m0 + wm * 32 + mt * 16 + g;
        #pragma unroll
        for (int nt = 0; nt < 8; nt++) {
            int col = colbase + nt * 8;
            if (r0 < n)
                *(float2*)&outp[(size_t)r0 * C_OUT + col] =
                    make_float2(acc[mt][nt][0], acc[mt][nt][1]);
            if (r0 + 8 < n)
                *(float2*)&outp[(size_t)(r0 + 8) * C_OUT + col] =
                    make_float2(acc[mt][nt][2], acc[mt][nt][3]);
        }
    }
}

// ------------------------------ CSR build ----------------------------------

__global__ void k_degree(const void* src, int E) {
    int e = blockIdx.x * blockDim.x + threadIdx.x;
    if (e < E) atomicAdd(&g_deg[get_idx(src, e)], 1);
}

__global__ void k_scan(int n) {
    __shared__ int wsum[32];
    int t = threadIdx.x, lane = t & 31, wid = t >> 5;
    int carry = 0;
    for (int base = 0; base < n; base += 1024) {
        int i = base + t;
        int v = (i < n) ? g_deg[i] : 0;
        int x = v;
        #pragma unroll
        for (int o = 1; o < 32; o <<= 1) {
            int nb = __shfl_up_sync(0xffffffffu, x, o);
            if (lane >= o) x += nb;
        }
        if (lane == 31) wsum[wid] = x;
        __syncthreads();
        if (wid == 0) {
            int s = wsum[lane];
            #pragma unroll
            for (int o = 1; o < 32; o <<= 1) {
                int nb = __shfl_up_sync(0xffffffffu, s, o);
                if (lane >= o) s += nb;
            }
            wsum[lane] = s;
        }
        __syncthreads();
        int warpoff = (wid == 0) ? 0 : wsum[wid - 1];
        int incl = warpoff + x;
        if (i < n) g_off[i] = carry + incl - v;
        int total = wsum[31];
        __syncthreads();
        carry += total;
    }
    if (t == 0) g_off[n] = carry;
}

__global__ void k_scatter(const void* src, const void* dst, int E) {
    int e = blockIdx.x * blockDim.x + threadIdx.x;
    if (e < E) {
        int s = get_idx(src, e);
        int d = get_idx(dst, e);
        int p = atomicAdd(&g_cur[s], 1);
        g_dsts[g_off[s] + p] = d;
    }
}

// ----------------------------- edge gather-max ------------------------------

__device__ __forceinline__ void max4(float4& m, float4 r) {
    m.x = fmaxf(m.x, r.x); m.y = fmaxf(m.y, r.y);
    m.z = fmaxf(m.z, r.z); m.w = fmaxf(m.w, r.w);
}

__global__ __launch_bounds__(64) void k_edge(float* __restrict__ out) {
    int s = blockIdx.x;
    int t = threadIdx.x;
    int start = g_off[s], end = g_off[s + 1];
    float4 m = make_float4(-INFINITY, -INFINITY, -INFINITY, -INFINITY);
    int i = start;
    for (; i + 8 <= end; i += 8) {
        int d[8];
        #pragma unroll
        for (int q = 0; q < 8; q++) d[q] = g_dsts[i + q];
        float4 r[8];
        #pragma unroll
        for (int q = 0; q < 8; q++)
            r[q] = ((const float4*)&g_u[(size_t)d[q] * C_OUT])[t];
        #pragma unroll
        for (int q = 0; q < 8; q++) max4(m, r[q]);
    }
    for (; i < end; i++) {
        float4 r = ((const float4*)&g_u[(size_t)g_dsts[i] * C_OUT])[t];
        max4(m, r);
    }
    float4 res;
    if (end > start) {
        float4 v = ((const float4*)&g_v[(size_t)s * C_OUT])[t];
        res.x = fmaxf(v.x + m.x, 0.0f);
        res.y = fmaxf(v.y + m.y, 0.0f);
        res.z = fmaxf(v.z + m.z, 0.0f);
        res.w = fmaxf(v.w + m.w, 0.0f);
    } else {
        res = make_float4(0.0f, 0.0f, 0.0f, 0.0f);
    }
    ((float4*)out)[(size_t)s * 64 + t] = res;
}

// --------------------------------- BN ---------------------------------------

__global__ void k_bnstat(const float* __restrict__ agg, int n) {
    int t = threadIdx.x;
    int r0 = blockIdx.x * 256;
    int r1 = min(r0 + 256, n);
    float s = 0.0f, s2 = 0.0f;
    for (int r = r0; r < r1; r++) {
        float v = agg[(size_t)r * C_OUT + t];
        s += v; s2 += v * v;
    }
    atomicAdd(&g_sum[t], s);
    atomicAdd(&g_sumsq[t], s2);
}

__global__ void k_bnfin(const float* __restrict__ gamma,
                        const float* __restrict__ beta, int n) {
    int t = threadIdx.x;
    float inv_n = 1.0f / (float)n;
    float mean = g_sum[t] * inv_n;
    float var  = g_sumsq[t] * inv_n - mean * mean;
    float rs = rsqrtf(var + BN_EPS);
    float sc = rs * gamma[t];
    g_scale[t] = sc;
    g_bias[t]  = beta[t] - mean * sc;
}

__global__ void k_bnapply(float4* __restrict__ out, int total4) {
    int i = blockIdx.x * blockDim.x + threadIdx.x;
    if (i < total4) {
        int c = i & 63;
        float4 v  = out[i];
        float4 sc = ((const float4*)g_scale)[c];
        float4 bi = ((const float4*)g_bias)[c];
        v.x = fmaxf(fmaf(v.x, sc.x, bi.x), 0.0f);
        v.y = fmaxf(fmaf(v.y, sc.y, bi.y), 0.0f);
        v.z = fmaxf(fmaf(v.z, sc.z, bi.z), 0.0f);
        v.w = fmaxf(fmaf(v.w, sc.w, bi.w), 0.0f);
        out[i] = v;
    }
}

// -------------------------------- launcher ----------------------------------

extern "C" void kernel_launch(void* const* d_in, const int* in_sizes, int n_in,
                              void* d_out, int out_size) {
    const float* x     = (const float*)d_in[0];
    const void*  src   = d_in[1];
    const void*  dst   = d_in[2];
    const float* theta = (const float*)d_in[3];
    const float* phi   = (const float*)d_in[4];
    const float* gamma = (const float*)d_in[5];
    const float* beta  = (const float*)d_in[6];
    float* out = (float*)d_out;

    int n = in_sizes[0] / C_IN;     // 50000
    int E = in_sizes[1];            // 800000

    k_detect<<<1, 32>>>((const unsigned int*)src);
    k_zero<<<(n + 255) / 256, 256>>>(n);
    k_wsplit<<<512, 192>>>(theta, phi);
    dim3 ggrid((n + 127) / 128, 4);
    k_gemm_mma<<<ggrid, 256>>>(x, n);                // at captured launch index
    k_degree<<<(E + 255) / 256, 256>>>(src, E);
    k_scan<<<1, 1024>>>(n);
    k_scatter<<<(E + 255) / 256, 256>>>(src, dst, E);
    k_edge<<<n, 64>>>(out);
    k_bnstat<<<(n + 255) / 256, 256>>>(out, n);
    k_bnfin<<<1, C_OUT>>>(gamma, beta, n);
    int total4 = n * 64;
    k_bnapply<<<(total4 + 255) / 256, 256>>>((float4*)out, total4);
}

// round 5
// speedup vs baseline: 1.9833x; 1.0970x over previous
#include <cuda_runtime.h>
#include <cuda_bf16.h>
#include <cuda_fp16.h>
#include <math.h>
#include <stdint.h>

// ---------------------------------------------------------------------------
// EdgeConv restructured:
//   u = x @ theta^T            [N, 256]   (stored fp16 for gather phase)
//   v = x @ (phi - theta)^T    [N, 256]   (fp32)
//   M[s,c] = max over edges (src=s) of u[dst,c]      (CSR gather-max, hmax2)
//   agg[s,c] = deg>0 ? relu(v[s,c] + M[s,c]) : 0
//   out = relu(BN(agg))
// GEMM: mma.sync bf16 split-precision K-concat, cp.async double-buffered.
// ---------------------------------------------------------------------------

#define MAX_NODES 50000
#define NODES_PAD 50048          // 391 * 128
#define MAX_EDGES 800000
#define C_IN 128
#define C_OUT 256
#define BN_EPS 1e-5f

__device__ uint32_t g_xc[NODES_PAD * 128];   // bf16 pairs [n][256]: cols 0-127 hi, 128-255 lo
__device__ uint32_t g_uh[MAX_NODES * 128];   // half2 u [n][256]
__device__ float    g_v[MAX_NODES * C_OUT];
__device__ uint32_t g_wc[512 * 192];   // bf16 pairs: [512 rows][384 cols] = [wh | wl | wh]
__device__ int      g_deg[MAX_NODES];
__device__ int      g_cur[MAX_NODES];
__device__ int      g_off[MAX_NODES + 1];
__device__ int      g_dsts[MAX_EDGES];
__device__ float    g_sum[C_OUT];
__device__ float    g_sumsq[C_OUT];
__device__ float    g_scale[C_OUT];
__device__ float    g_bias[C_OUT];
__device__ int      g_is64;

// --------------------------- helpers ----------------------------------------

__device__ __forceinline__ uint32_t smem_u32(const void* p) {
    uint32_t a;
    asm("{ .reg .u64 t; cvta.to.shared.u64 t, %1; cvt.u32.u64 %0, t; }" : "=r"(a) : "l"(p));
    return a;
}
#define CP16(dst, src) asm volatile("cp.async.cg.shared.global [%0], [%1], 16;" :: "r"(dst), "l"(src))
#define CP_COMMIT()    asm volatile("cp.async.commit_group;" ::: "memory")
#define CP_WAIT(k)     asm volatile("cp.async.wait_group %0;" :: "n"(k) : "memory")

__device__ __forceinline__ void ldsm4(uint32_t& r0, uint32_t& r1, uint32_t& r2, uint32_t& r3,
                                      uint32_t addr) {
    asm volatile("ldmatrix.sync.aligned.m8n8.x4.shared.b16 {%0,%1,%2,%3}, [%4];"
                 : "=r"(r0), "=r"(r1), "=r"(r2), "=r"(r3) : "r"(addr));
}
__device__ __forceinline__ void mma16816(float* c, uint32_t a0, uint32_t a1, uint32_t a2,
                                         uint32_t a3, uint32_t b0, uint32_t b1) {
    asm volatile(
        "mma.sync.aligned.m16n8k16.row.col.f32.bf16.bf16.f32 "
        "{%0,%1,%2,%3}, {%4,%5,%6,%7}, {%8,%9}, {%0,%1,%2,%3};"
        : "+f"(c[0]), "+f"(c[1]), "+f"(c[2]), "+f"(c[3])
        : "r"(a0), "r"(a1), "r"(a2), "r"(a3), "r"(b0), "r"(b1));
}

// --------------------------- index dtype handling ---------------------------

__global__ void k_detect(const unsigned int* src_words) {
    if (threadIdx.x == 0) {
        unsigned int o = 0;
        for (int i = 1; i < 128; i += 2) o |= src_words[i];
        g_is64 = (o == 0) ? 1 : 0;
    }
}
__device__ __forceinline__ int get_idx(const void* p, int e) {
    return g_is64 ? (int)((const long long*)p)[e] : ((const int*)p)[e];
}

// --------------------------------- prep -------------------------------------

__global__ void k_zero(int n) {
    int i = blockIdx.x * blockDim.x + threadIdx.x;
    if (i < n) { g_deg[i] = 0; g_cur[i] = 0; }
    if (i < C_OUT) { g_sum[i] = 0.0f; g_sumsq[i] = 0.0f; }
}

// split x rows into bf16 hi/lo pairs: g_xc[r][p]=hi pair, g_xc[r][64+p]=lo pair
__global__ void k_xsplit(const float* __restrict__ x, int n) {
    int i = blockIdx.x * blockDim.x + threadIdx.x;   // over n*64 pairs
    if (i >= n * 64) return;
    int r = i >> 6, p = i & 63;
    float2 xv = *(const float2*)&x[(size_t)r * C_IN + 2 * p];
    __nv_bfloat16 h0 = __float2bfloat16(xv.x), h1 = __float2bfloat16(xv.y);
    __nv_bfloat16 l0 = __float2bfloat16(xv.x - __bfloat162float(h0));
    __nv_bfloat16 l1 = __float2bfloat16(xv.y - __bfloat162float(h1));
    g_xc[(size_t)r * 128 + p] =
        (uint32_t)__bfloat16_as_ushort(h0) | ((uint32_t)__bfloat16_as_ushort(h1) << 16);
    g_xc[(size_t)r * 128 + 64 + p] =
        (uint32_t)__bfloat16_as_ushort(l0) | ((uint32_t)__bfloat16_as_ushort(l1) << 16);
}

// concat weight table: row j (0-255: theta, 256-511: phi-theta),
// col segments [0:128)=hi, [128:256)=lo, [256:384)=hi
__global__ void k_wsplit(const float* __restrict__ theta, const float* __restrict__ phi) {
    int j = blockIdx.x;      // 0..511
    int p = threadIdx.x;     // 0..191 (bf16 pair index)
    int seg = p >> 6;
    int kk = (p & 63) * 2;
    float w0, w1;
    if (j < C_OUT) {
        w0 = theta[j * C_IN + kk];
        w1 = theta[j * C_IN + kk + 1];
    } else {
        int jj = j - C_OUT;
        w0 = phi[jj * C_IN + kk]     - theta[jj * C_IN + kk];
        w1 = phi[jj * C_IN + kk + 1] - theta[jj * C_IN + kk + 1];
    }
    __nv_bfloat16 h0 = __float2bfloat16(w0), h1 = __float2bfloat16(w1);
    uint32_t out;
    if (seg == 1) {
        __nv_bfloat16 l0 = __float2bfloat16(w0 - __bfloat162float(h0));
        __nv_bfloat16 l1 = __float2bfloat16(w1 - __bfloat162float(h1));
        out = (uint32_t)__bfloat16_as_ushort(l0) | ((uint32_t)__bfloat16_as_ushort(l1) << 16);
    } else {
        out = (uint32_t)__bfloat16_as_ushort(h0) | ((uint32_t)__bfloat16_as_ushort(h1) << 16);
    }
    g_wc[j * 192 + p] = out;
}

// ------------------------------ HMMA GEMM -----------------------------------
// CTA 128x128, K'=384 in 6 chunks of 64, cp.async 2-stage double buffer.
// smem rows padded to 72 bf16 (144 B): ldmatrix conflict-free.

#define SROW   72
#define ASTAGE 18432                  // 128 * 144
#define SM_GEMM (4 * ASTAGE)          // A0 A1 B0 B1

__constant__ int c_aoffp[6] = {0, 32, 0, 32, 64, 96};   // A pair offsets per chunk

__global__ __launch_bounds__(256) void k_gemm_mma(int n) {
    extern __shared__ char smem[];
    uint32_t sb = smem_u32(smem);
    int tid = threadIdx.x;
    int wid = tid >> 5, lane = tid & 31;
    int m0 = blockIdx.x * 128;
    int n0 = blockIdx.y * 128;
    int wm = wid & 3, wn = wid >> 2;

    float acc[2][8][4];
    #pragma unroll
    for (int a = 0; a < 2; a++)
        #pragma unroll
        for (int b = 0; b < 8; b++)
            #pragma unroll
            for (int q = 0; q < 4; q++) acc[a][b][q] = 0.0f;

    int frow = tid >> 3, fq = tid & 7;        // fill: 32 rows per pass, 4 passes

    // per-chunk stage fill via cp.async
    auto load_stage = [&](int c, int s) {
        uint32_t aBase = sb + s * ASTAGE;
        uint32_t bBase = sb + 2 * ASTAGE + s * ASTAGE;
        const uint32_t* asrc0 = g_xc + (size_t)(m0 + frow) * 128 + c_aoffp[c] + fq * 4;
        const uint32_t* bsrc0 = g_wc + (size_t)(n0 + frow) * 192 + c * 32 + fq * 4;
        #pragma unroll
        for (int k = 0; k < 4; k++) {
            CP16(aBase + (frow + k * 32) * 144 + fq * 16, asrc0 + (size_t)k * 32 * 128);
            CP16(bBase + (frow + k * 32) * 144 + fq * 16, bsrc0 + (size_t)k * 32 * 192);
        }
        CP_COMMIT();
    };

    uint32_t a_lane_row = (uint32_t)(wm * 32 + (lane & 15));
    uint32_t a_lane_kh  = (uint32_t)((lane >> 4) * 8);
    uint32_t b_lane_row = (uint32_t)(wn * 64 + ((lane >> 4) * 8) + (lane & 7));
    uint32_t b_lane_kh  = (uint32_t)(((lane >> 3) & 1) * 8);

    load_stage(0, 0);
    for (int c = 0; c < 6; c++) {
        int s = c & 1;
        if (c < 5) { load_stage(c + 1, s ^ 1); CP_WAIT(1); }
        else       { CP_WAIT(0); }
        __syncthreads();

        uint32_t aB = sb + s * ASTAGE;
        uint32_t bB = sb + 2 * ASTAGE + s * ASTAGE;
        #pragma unroll
        for (int kk = 0; kk < 4; kk++) {
            uint32_t af[2][4];
            #pragma unroll
            for (int mt = 0; mt < 2; mt++) {
                uint32_t addr = aB + (a_lane_row + mt * 16) * (SROW * 2)
                              + (kk * 16 + a_lane_kh) * 2;
                ldsm4(af[mt][0], af[mt][1], af[mt][2], af[mt][3], addr);
            }
            uint32_t bf[8][2];
            #pragma unroll
            for (int np = 0; np < 4; np++) {
                uint32_t addr = bB + (b_lane_row + np * 16) * (SROW * 2)
                              + (kk * 16 + b_lane_kh) * 2;
                uint32_t r0, r1, r2, r3;
                ldsm4(r0, r1, r2, r3, addr);
                bf[np * 2][0] = r0; bf[np * 2][1] = r1;
                bf[np * 2 + 1][0] = r2; bf[np * 2 + 1][1] = r3;
            }
            #pragma unroll
            for (int mt = 0; mt < 2; mt++)
                #pragma unroll
                for (int nt = 0; nt < 8; nt++)
                    mma16816(acc[mt][nt], af[mt][0], af[mt][1], af[mt][2], af[mt][3],
                             bf[nt][0], bf[nt][1]);
        }
        __syncthreads();
    }

    // ---- epilogue ----
    int g = lane >> 2, tig = lane & 3;
    bool is_u = (blockIdx.y < 2);
    int colbase = (int)(blockIdx.y & 1) * 128 + wn * 64 + tig * 2;
    #pragma unroll
    for (int mt = 0; mt < 2; mt++) {
        int r0 = m0 + wm * 32 + mt * 16 + g;
        #pragma unroll
        for (int nt = 0; nt < 8; nt++) {
            int col = colbase + nt * 8;
            if (is_u) {
                if (r0 < n) {
                    __half2 h = __floats2half2_rn(acc[mt][nt][0], acc[mt][nt][1]);
                    g_uh[(size_t)r0 * 128 + (col >> 1)] = *(uint32_t*)&h;
                }
                if (r0 + 8 < n) {
                    __half2 h = __floats2half2_rn(acc[mt][nt][2], acc[mt][nt][3]);
                    g_uh[(size_t)(r0 + 8) * 128 + (col >> 1)] = *(uint32_t*)&h;
                }
            } else {
                if (r0 < n)
                    *(float2*)&g_v[(size_t)r0 * C_OUT + col] =
                        make_float2(acc[mt][nt][0], acc[mt][nt][1]);
                if (r0 + 8 < n)
                    *(float2*)&g_v[(size_t)(r0 + 8) * C_OUT + col] =
                        make_float2(acc[mt][nt][2], acc[mt][nt][3]);
            }
        }
    }
}

// ------------------------------ CSR build ----------------------------------

__global__ void k_degree(const void* src, int E) {
    int e = blockIdx.x * blockDim.x + threadIdx.x;
    if (e < E) atomicAdd(&g_deg[get_idx(src, e)], 1);
}

__global__ void k_scan(int n) {
    __shared__ int wsum[32];
    int t = threadIdx.x, lane = t & 31, wid = t >> 5;
    int carry = 0;
    for (int base = 0; base < n; base += 1024) {
        int i = base + t;
        int v = (i < n) ? g_deg[i] : 0;
        int x = v;
        #pragma unroll
        for (int o = 1; o < 32; o <<= 1) {
            int nb = __shfl_up_sync(0xffffffffu, x, o);
            if (lane >= o) x += nb;
        }
        if (lane == 31) wsum[wid] = x;
        __syncthreads();
        if (wid == 0) {
            int s = wsum[lane];
            #pragma unroll
            for (int o = 1; o < 32; o <<= 1) {
                int nb = __shfl_up_sync(0xffffffffu, s, o);
                if (lane >= o) s += nb;
            }
            wsum[lane] = s;
        }
        __syncthreads();
        int warpoff = (wid == 0) ? 0 : wsum[wid - 1];
        int incl = warpoff + x;
        if (i < n) g_off[i] = carry + incl - v;
        int total = wsum[31];
        __syncthreads();
        carry += total;
    }
    if (t == 0) g_off[n] = carry;
}

__global__ void k_scatter(const void* src, const void* dst, int E) {
    int e = blockIdx.x * blockDim.x + threadIdx.x;
    if (e < E) {
        int s = get_idx(src, e);
        int d = get_idx(dst, e);
        int p = atomicAdd(&g_cur[s], 1);
        g_dsts[g_off[s] + p] = d;
    }
}

// ----------------------------- edge gather-max ------------------------------
// 4 nodes per 128-thread CTA; 32 threads per node; thread owns 8 channels
// (uint4 = 4x half2); hmax2 accumulate; combine with fp32 v.

__global__ __launch_bounds__(128) void k_edge(float* __restrict__ out, int n) {
    int node = blockIdx.x * 4 + (threadIdx.x >> 5);
    int t = threadIdx.x & 31;
    if (node >= n) return;
    int start = g_off[node], end = g_off[node + 1];

    __half2 m0 = __float2half2_rn(-65504.0f), m1 = m0, m2 = m0, m3 = m0;
    int i = start;
    for (; i + 8 <= end; i += 8) {
        int d[8];
        #pragma unroll
        for (int q = 0; q < 8; q++) d[q] = g_dsts[i + q];
        uint4 r[8];
        #pragma unroll
        for (int q = 0; q < 8; q++)
            r[q] = *(const uint4*)(g_uh + (size_t)d[q] * 128 + t * 4);
        #pragma unroll
        for (int q = 0; q < 8; q++) {
            m0 = __hmax2(m0, *(__half2*)&r[q].x);
            m1 = __hmax2(m1, *(__half2*)&r[q].y);
            m2 = __hmax2(m2, *(__half2*)&r[q].z);
            m3 = __hmax2(m3, *(__half2*)&r[q].w);
        }
    }
    for (; i < end; i++) {
        uint4 r = *(const uint4*)(g_uh + (size_t)g_dsts[i] * 128 + t * 4);
        m0 = __hmax2(m0, *(__half2*)&r.x);
        m1 = __hmax2(m1, *(__half2*)&r.y);
        m2 = __hmax2(m2, *(__half2*)&r.z);
        m3 = __hmax2(m3, *(__half2*)&r.w);
    }

    float4 o0, o1;
    if (end > start) {
        float4 v0 = *(const float4*)&g_v[(size_t)node * C_OUT + t * 8];
        float4 v1 = *(const float4*)&g_v[(size_t)node * C_OUT + t * 8 + 4];
        float2 f0 = __half22float2(m0), f1 = __half22float2(m1);
        float2 f2 = __half22float2(m2), f3 = __half22float2(m3);
        o0 = make_float4(fmaxf(v0.x + f0.x, 0.f), fmaxf(v0.y + f0.y, 0.f),
                         fmaxf(v0.z + f1.x, 0.f), fmaxf(v0.w + f1.y, 0.f));
        o1 = make_float4(fmaxf(v1.x + f2.x, 0.f), fmaxf(v1.y + f2.y, 0.f),
                         fmaxf(v1.z + f3.x, 0.f), fmaxf(v1.w + f3.y, 0.f));
    } else {
        o0 = make_float4(0.f, 0.f, 0.f, 0.f);
        o1 = o0;
    }
    *(float4*)&out[(size_t)node * C_OUT + t * 8] = o0;
    *(float4*)&out[(size_t)node * C_OUT + t * 8 + 4] = o1;
}

// --------------------------------- BN ---------------------------------------

__global__ void k_bnstat(const float* __restrict__ agg, int n) {
    int t = threadIdx.x;
    int r0 = blockIdx.x * 256;
    int r1 = min(r0 + 256, n);
    float s = 0.0f, s2 = 0.0f;
    for (int r = r0; r < r1; r++) {
        float v = agg[(size_t)r * C_OUT + t];
        s += v; s2 += v * v;
    }
    atomicAdd(&g_sum[t], s);
    atomicAdd(&g_sumsq[t], s2);
}

__global__ void k_bnfin(const float* __restrict__ gamma,
                        const float* __restrict__ beta, int n) {
    int t = threadIdx.x;
    float inv_n = 1.0f / (float)n;
    float mean = g_sum[t] * inv_n;
    float var  = g_sumsq[t] * inv_n - mean * mean;
    float rs = rsqrtf(var + BN_EPS);
    float sc = rs * gamma[t];
    g_scale[t] = sc;
    g_bias[t]  = beta[t] - mean * sc;
}

__global__ void k_bnapply(float4* __restrict__ out, int total4) {
    int i = blockIdx.x * blockDim.x + threadIdx.x;
    if (i < total4) {
        int c = i & 63;
        float4 v  = out[i];
        float4 sc = ((const float4*)g_scale)[c];
        float4 bi = ((const float4*)g_bias)[c];
        v.x = fmaxf(fmaf(v.x, sc.x, bi.x), 0.0f);
        v.y = fmaxf(fmaf(v.y, sc.y, bi.y), 0.0f);
        v.z = fmaxf(fmaf(v.z, sc.z, bi.z), 0.0f);
        v.w = fmaxf(fmaf(v.w, sc.w, bi.w), 0.0f);
        out[i] = v;
    }
}

// -------------------------------- launcher ----------------------------------

extern "C" void kernel_launch(void* const* d_in, const int* in_sizes, int n_in,
                              void* d_out, int out_size) {
    const float* x     = (const float*)d_in[0];
    const void*  src   = d_in[1];
    const void*  dst   = d_in[2];
    const float* theta = (const float*)d_in[3];
    const float* phi   = (const float*)d_in[4];
    const float* gamma = (const float*)d_in[5];
    const float* beta  = (const float*)d_in[6];
    float* out = (float*)d_out;

    int n = in_sizes[0] / C_IN;     // 50000
    int E = in_sizes[1];            // 800000

    static int smem_set = 0;
    if (!smem_set) {
        cudaFuncSetAttribute(k_gemm_mma, cudaFuncAttributeMaxDynamicSharedMemorySize, SM_GEMM);
        smem_set = 1;
    }

    k_detect<<<1, 32>>>((const unsigned int*)src);
    k_xsplit<<<(n * 64 + 255) / 256, 256>>>(x, n);
    k_wsplit<<<512, 192>>>(theta, phi);
    dim3 ggrid((n + 127) / 128, 4);
    k_gemm_mma<<<ggrid, 256, SM_GEMM>>>(n);          // at captured launch index
    k_zero<<<(n + 255) / 256, 256>>>(n);
    k_degree<<<(E + 255) / 256, 256>>>(src, E);
    k_scan<<<1, 1024>>>(n);
    k_scatter<<<(E + 255) / 256, 256>>>(src, dst, E);
    k_edge<<<(n + 3) / 4, 128>>>(out, n);
    k_bnstat<<<(n + 255) / 256, 256>>>(out, n);
    k_bnfin<<<1, C_OUT>>>(gamma, beta, n);
    int total4 = n * 64;
    k_bnapply<<<(total4 + 255) / 256, 256>>>((float4*)out, total4);
}